// round 3
// baseline (speedup 1.0000x reference)
#include <cuda_runtime.h>
#include <cuda_bf16.h>
#include <math.h>

// Problem constants
#define B_   64
#define D_   2048
#define N_   16384
#define TINV 20.0f          // 1 / TEMP, TEMP = 0.05

// GEMM tiling
#define TN_  128            // n columns per block
#define TK_  32             // k per stage
#define NBLK_ (N_ / TN_)    // 128 blocks
#define NKT   (D_ / TK_)    // 64 k-tiles
#define XSS  68             // xs row stride (64 + 4 pad), floats
#define FSS  132            // fs row stride (128 + 4 pad), floats
#define SMEM_BYTES ((2 * TK_ * XSS + 2 * TK_ * FSS) * 4)   // 51200 B

// Scratch (no allocations allowed -> __device__ globals)
__device__ float  g_inv_norm[B_];
__device__ float4 g_part[B_ * NBLK_];   // per (row, block): max, sumexp, W, Zt
__device__ float  g_row_loss[B_];

// ---------------------------------------------------------------------------
// Kernel 1: inverse L2 norm of each input row
// ---------------------------------------------------------------------------
__global__ void norm_kernel(const float* __restrict__ x) {
    __shared__ float red[8];
    const int b = blockIdx.x;
    const float4* row = (const float4*)(x + (size_t)b * D_);
    float s = 0.f;
    for (int i = threadIdx.x; i < D_ / 4; i += blockDim.x) {
        float4 v = row[i];
        s += v.x * v.x + v.y * v.y + v.z * v.z + v.w * v.w;
    }
#pragma unroll
    for (int o = 16; o; o >>= 1) s += __shfl_xor_sync(0xffffffffu, s, o);
    if ((threadIdx.x & 31) == 0) red[threadIdx.x >> 5] = s;
    __syncthreads();
    if (threadIdx.x < 8) {
        float v = red[threadIdx.x];
#pragma unroll
        for (int o = 4; o; o >>= 1) v += __shfl_xor_sync(0x000000ffu, v, o);
        if (threadIdx.x == 0) g_inv_norm[b] = rsqrtf(v);
    }
}

// ---------------------------------------------------------------------------
// Kernel 2: GEMM (64 x TN_ tile per block) + fused softmax-CE partials
//   logits[m,n] = dot(x[m], feat[n]) * inv_norm[m] / TEMP
//   partials per (m, block): tile max, tile sum(exp(l - max)),
//                            W = sum(exp(t)*l), Zt = sum(exp(t))
// ---------------------------------------------------------------------------
__global__ void __launch_bounds__(128, 1)
gemm_kernel(const float* __restrict__ x, const float* __restrict__ feat,
            const float* __restrict__ targets)
{
    extern __shared__ float smem[];
    float* xs = smem;                  // [2][TK_][XSS]  k-major, transposed x tile
    float* fs = smem + 2 * TK_ * XSS;  // [2][TK_][FSS]  k-major, transposed f tile

    const int tid = threadIdx.x;
    const int tn  = tid & 15;          // 16 n-groups
    const int tm  = tid >> 4;          // 8 m-groups
    const int n0  = blockIdx.x * TN_;

    // feature-tile loader mapping (coalesced: 8 threads cover one row's 128B)
    const int fr = tid >> 3;           // 0..15 (+16*i)
    const int fc = tid & 7;            // float4 column 0..7

    // 8 m x 8 n accumulators (scalar fp32 — f32x2 is sm_103a-only)
    float acc[8][8];
#pragma unroll
    for (int i = 0; i < 8; i++)
#pragma unroll
        for (int j = 0; j < 8; j++) acc[i][j] = 0.f;

    float4 fstg[8];
    float4 xstg[4];

    const float* fbase = feat + (size_t)n0 * D_;

    // ---- prologue: load k-tile 0 into registers, then smem buffer 0 ----
#pragma unroll
    for (int i = 0; i < 8; i++)
        fstg[i] = *(const float4*)(fbase + (size_t)(fr + 16 * i) * D_ + 4 * fc);
#pragma unroll
    for (int i = 0; i < 4; i++) {
        int idx = tid + 128 * i;
        xstg[i] = *(const float4*)(x + (size_t)(idx >> 3) * D_ + 4 * (idx & 7));
    }
#pragma unroll
    for (int i = 0; i < 8; i++) {
        float* p = fs + (4 * fc) * FSS + (fr + 16 * i);
        p[0] = fstg[i].x; p[FSS] = fstg[i].y; p[2 * FSS] = fstg[i].z; p[3 * FSS] = fstg[i].w;
    }
#pragma unroll
    for (int i = 0; i < 4; i++) {
        int idx = tid + 128 * i;
        float* p = xs + (4 * (idx & 7)) * XSS + (idx >> 3);
        p[0] = xstg[i].x; p[XSS] = xstg[i].y; p[2 * XSS] = xstg[i].z; p[3 * XSS] = xstg[i].w;
    }
    __syncthreads();

    int buf = 0;
    for (int kt = 0; kt < NKT; kt++) {
        // prefetch next k-tile into registers (hides DRAM/L2 latency under FMAs)
        if (kt + 1 < NKT) {
            const int k0 = (kt + 1) * TK_;
#pragma unroll
            for (int i = 0; i < 8; i++)
                fstg[i] = *(const float4*)(fbase + (size_t)(fr + 16 * i) * D_ + k0 + 4 * fc);
#pragma unroll
            for (int i = 0; i < 4; i++) {
                int idx = tid + 128 * i;
                xstg[i] = *(const float4*)(x + (size_t)(idx >> 3) * D_ + k0 + 4 * (idx & 7));
            }
        }

        // compute on current buffer
        const float* xsb = xs + buf * TK_ * XSS;
        const float* fsb = fs + buf * TK_ * FSS;
#pragma unroll 8
        for (int k = 0; k < TK_; k++) {
            float4 a0 = *(const float4*)(xsb + k * XSS + 4 * tm);
            float4 a1 = *(const float4*)(xsb + k * XSS + 32 + 4 * tm);
            float4 b0 = *(const float4*)(fsb + k * FSS + 4 * tn);
            float4 b1 = *(const float4*)(fsb + k * FSS + 64 + 4 * tn);
            float av[8] = { a0.x, a0.y, a0.z, a0.w, a1.x, a1.y, a1.z, a1.w };
            float bv[8] = { b0.x, b0.y, b0.z, b0.w, b1.x, b1.y, b1.z, b1.w };
#pragma unroll
            for (int i = 0; i < 8; i++)
#pragma unroll
                for (int j = 0; j < 8; j++)
                    acc[i][j] = fmaf(av[i], bv[j], acc[i][j]);
        }

        // write prefetched tile into the other buffer; one sync/iter suffices
        if (kt + 1 < NKT) {
            const int nb = buf ^ 1;
#pragma unroll
            for (int i = 0; i < 8; i++) {
                float* p = fs + nb * TK_ * FSS + (4 * fc) * FSS + (fr + 16 * i);
                p[0] = fstg[i].x; p[FSS] = fstg[i].y; p[2 * FSS] = fstg[i].z; p[3 * FSS] = fstg[i].w;
            }
#pragma unroll
            for (int i = 0; i < 4; i++) {
                int idx = tid + 128 * i;
                float* p = xs + nb * TK_ * XSS + (4 * (idx & 7)) * XSS + (idx >> 3);
                p[0] = xstg[i].x; p[XSS] = xstg[i].y; p[2 * XSS] = xstg[i].z; p[3 * XSS] = xstg[i].w;
            }
            __syncthreads();
            buf = nb;
        }
    }

    // ---- epilogue: scale to logits, fuse soft-CE partials, half-warp reduce ----
#pragma unroll
    for (int i = 0; i < 8; i++) {
        const int m = (i < 4) ? (4 * tm + i) : (32 + 4 * tm + (i - 4));
        const float s = g_inv_norm[m] * TINV;

        float l[8];
#pragma unroll
        for (int j = 0; j < 8; j++) l[j] = acc[i][j] * s;

        // this thread's n values: {n0+4tn+j} and {n0+64+4tn+j}
        const float* tr = targets + (size_t)m * N_ + n0;
        float4 t0 = *(const float4*)(tr + 4 * tn);
        float4 t1 = *(const float4*)(tr + 64 + 4 * tn);
        float et[8] = { __expf(t0.x), __expf(t0.y), __expf(t0.z), __expf(t0.w),
                        __expf(t1.x), __expf(t1.y), __expf(t1.z), __expf(t1.w) };

        float mx = l[0];
#pragma unroll
        for (int j = 1; j < 8; j++) mx = fmaxf(mx, l[j]);
        float se = 0.f, W = 0.f, Zt = 0.f;
#pragma unroll
        for (int j = 0; j < 8; j++) {
            se += __expf(l[j] - mx);
            W  += et[j] * l[j];
            Zt += et[j];
        }

        // reduce across the 16 lanes sharing this m (xor < 16 stays in-half)
#pragma unroll
        for (int off = 8; off; off >>= 1) {
            float omx = __shfl_xor_sync(0xffffffffu, mx, off);
            float ose = __shfl_xor_sync(0xffffffffu, se, off);
            float oW  = __shfl_xor_sync(0xffffffffu, W,  off);
            float oZ  = __shfl_xor_sync(0xffffffffu, Zt, off);
            float nm = fmaxf(mx, omx);
            se = se * __expf(mx - nm) + ose * __expf(omx - nm);
            mx = nm; W += oW; Zt += oZ;
        }
        if (tn == 0)
            g_part[(size_t)m * NBLK_ + blockIdx.x] = make_float4(mx, se, W, Zt);
    }
}

// ---------------------------------------------------------------------------
// Kernel 3: per-row merge of 128 block partials -> row loss = lse - W/Zt
// ---------------------------------------------------------------------------
__global__ void rowred_kernel() {
    const int m = blockIdx.x;
    const int t = threadIdx.x;   // 128 threads
    float4 p = g_part[(size_t)m * NBLK_ + t];
    float mx = p.x, se = p.y, W = p.z, Zt = p.w;
#pragma unroll
    for (int off = 16; off; off >>= 1) {
        float omx = __shfl_xor_sync(0xffffffffu, mx, off);
        float ose = __shfl_xor_sync(0xffffffffu, se, off);
        float oW  = __shfl_xor_sync(0xffffffffu, W,  off);
        float oZ  = __shfl_xor_sync(0xffffffffu, Zt, off);
        float nm = fmaxf(mx, omx);
        se = se * expf(mx - nm) + ose * expf(omx - nm);
        mx = nm; W += oW; Zt += oZ;
    }
    __shared__ float4 red[4];
    if ((t & 31) == 0) red[t >> 5] = make_float4(mx, se, W, Zt);
    __syncthreads();
    if (t == 0) {
        mx = red[0].x; se = red[0].y; W = red[0].z; Zt = red[0].w;
#pragma unroll
        for (int w = 1; w < 4; w++) {
            float4 q = red[w];
            float nm = fmaxf(mx, q.x);
            se = se * expf(mx - nm) + q.y * expf(q.x - nm);
            mx = nm; W += q.z; Zt += q.w;
        }
        g_row_loss[m] = (mx + logf(se)) - W / Zt;
    }
}

// ---------------------------------------------------------------------------
// Kernel 4: deterministic final sum / B  (no atomics -> bitwise deterministic)
// ---------------------------------------------------------------------------
__global__ void final_kernel(float* out) {
    const int t = threadIdx.x;   // 64 threads
    float v = g_row_loss[t];
#pragma unroll
    for (int off = 16; off; off >>= 1) v += __shfl_xor_sync(0xffffffffu, v, off);
    __shared__ float w0;
    if (t == 0) w0 = v;
    __syncthreads();
    if (t == 32) out[0] = (v + w0) * (1.0f / B_);
}

// ---------------------------------------------------------------------------
extern "C" void kernel_launch(void* const* d_in, const int* in_sizes, int n_in,
                              void* d_out, int out_size) {
    // Identify inputs by element count (robust to ordering); cid (64 ints) unused.
    const float* x  = nullptr;
    const float* tg = nullptr;
    const float* ft = nullptr;
    for (int i = 0; i < n_in; i++) {
        if      (in_sizes[i] == B_ * D_) x  = (const float*)d_in[i];
        else if (in_sizes[i] == B_ * N_) tg = (const float*)d_in[i];
        else if (in_sizes[i] == N_ * D_) ft = (const float*)d_in[i];
    }

    cudaFuncSetAttribute(gemm_kernel, cudaFuncAttributeMaxDynamicSharedMemorySize,
                         SMEM_BYTES);

    norm_kernel<<<B_, 256>>>(x);
    gemm_kernel<<<NBLK_, 128, SMEM_BYTES>>>(x, ft, tg);
    rowred_kernel<<<B_, 128>>>();
    final_kernel<<<1, 64>>>((float*)d_out);
}

// round 6
// speedup vs baseline: 2.5507x; 2.5507x over previous
#include <cuda_runtime.h>
#include <cuda_bf16.h>
#include <math.h>
#include <stdint.h>

// Problem constants
#define B_   64
#define D_   2048
#define N_   16384
#define TINV 20.0f          // 1 / TEMP

#define NBLK_ 128           // CTAs; each handles 128 feature rows
#define NKS   64            // k-stages (2048 / 32)
#define STG   4             // cp.async pipeline depth

// smem layout (bytes). A tile: 128 rows x 36 floats (pad) = 18432 B.
// B tile: 64 rows x 36 floats = 9216 B. Stage = 27648 B.
#define ASTR   36
#define SM_INVN   0                      // 64 floats
#define SM_HALF   256                    // 64 float4
#define SM_STAGE  1280
#define STGB      27648
#define BOFF      18432
#define SM_L      SM_STAGE               // alias: logits 128 x 65 fp32 (33280 B)
#define SMEM_TOTAL (SM_STAGE + STG * STGB)   // 111872 B

__device__ float  g_inv_norm[B_];
__device__ float4 g_part[B_ * NBLK_];
__device__ float  g_row_loss[B_];

__device__ __forceinline__ uint32_t smem_u32(const void* p) {
    uint32_t a;
    asm("{ .reg .u64 t; cvta.to.shared.u64 t, %1; cvt.u32.u64 %0, t; }" : "=r"(a) : "l"(p));
    return a;
}
#define CP16(dst, src) \
    asm volatile("cp.async.cg.shared.global [%0], [%1], 16;" :: "r"(dst), "l"(src) : "memory")
#define CP_COMMIT()  asm volatile("cp.async.commit_group;" ::: "memory")
#define CP_WAIT3()   asm volatile("cp.async.wait_group 3;" ::: "memory")

// ---------------------------------------------------------------------------
// Kernel 1: inverse L2 norm of each input row
// ---------------------------------------------------------------------------
__global__ void norm_kernel(const float* __restrict__ x) {
    __shared__ float red[8];
    const int b = blockIdx.x;
    const float4* row = (const float4*)(x + (size_t)b * D_);
    float s = 0.f;
    for (int i = threadIdx.x; i < D_ / 4; i += blockDim.x) {
        float4 v = row[i];
        s += v.x * v.x + v.y * v.y + v.z * v.z + v.w * v.w;
    }
#pragma unroll
    for (int o = 16; o; o >>= 1) s += __shfl_xor_sync(0xffffffffu, s, o);
    if ((threadIdx.x & 31) == 0) red[threadIdx.x >> 5] = s;
    __syncthreads();
    if (threadIdx.x < 8) {
        float v = red[threadIdx.x];
#pragma unroll
        for (int o = 4; o; o >>= 1) v += __shfl_xor_sync(0x000000ffu, v, o);
        if (threadIdx.x == 0) g_inv_norm[b] = rsqrtf(v);
    }
}

// ---------------------------------------------------------------------------
// Kernel 2: mma.sync tf32 GEMM  D[128 feat][64 batch] + fused CE partials
//   A = features tile (row-major, [feat][k]); B = x (col-major frag, [batch][k])
// ---------------------------------------------------------------------------
__global__ void __launch_bounds__(128, 1)
mma_kernel(const float* __restrict__ x, const float* __restrict__ feat,
           const float* __restrict__ targets)
{
    extern __shared__ char smem[];
    const uint32_t sb = smem_u32(smem);
    const int tid  = threadIdx.x;
    const int wid  = tid >> 5;
    const int lane = tid & 31;
    const int gid  = lane >> 2;        // fragment row group 0..7
    const int tig  = lane & 3;         // thread-in-group 0..3
    const int n0   = blockIdx.x * 128; // feature-row tile base
    const int m0   = 32 * wid;         // this warp's first feature row (in tile)

    float* invn = (float*)(smem + SM_INVN);
    if (tid < B_) invn[tid] = g_inv_norm[tid];

    // cp.async one k-stage (32 floats per row) into buffer s
    const float* fbase = feat + (size_t)n0 * D_;
    auto load_stage = [&](int ks, int s) {
        const uint32_t abase = sb + SM_STAGE + s * STGB;
#pragma unroll
        for (int i = 0; i < 8; i++) {            // A: 1024 16B chunks
            int id  = tid + 128 * i;
            int row = id >> 3, c = id & 7;
            CP16(abase + row * (ASTR * 4) + c * 16,
                 fbase + (size_t)row * D_ + ks * 32 + 4 * c);
        }
        const uint32_t bbase = abase + BOFF;
#pragma unroll
        for (int i = 0; i < 4; i++) {            // B: 512 16B chunks
            int id  = tid + 128 * i;
            int row = id >> 3, c = id & 7;
            CP16(bbase + row * (ASTR * 4) + c * 16,
                 x + (size_t)row * D_ + ks * 32 + 4 * c);
        }
    };

    float acc[2][8][4];
#pragma unroll
    for (int mt = 0; mt < 2; mt++)
#pragma unroll
        for (int nt = 0; nt < 8; nt++)
#pragma unroll
            for (int c = 0; c < 4; c++) acc[mt][nt][c] = 0.f;

    // prologue
#pragma unroll
    for (int s = 0; s < STG - 1; s++) { load_stage(s, s); CP_COMMIT(); }

    for (int j = 0; j < NKS; j++) {
        if (j + STG - 1 < NKS) load_stage(j + STG - 1, (j + STG - 1) & 3);
        CP_COMMIT();             // uniform group count (empty at tail)
        CP_WAIT3();              // ≤3 pending ⇒ stage j resident
        __syncthreads();

        const uint32_t* As = (const uint32_t*)(smem + SM_STAGE + (j & 3) * STGB);
        const uint32_t* Bs = (const uint32_t*)(smem + SM_STAGE + (j & 3) * STGB + BOFF);

#pragma unroll
        for (int kk = 0; kk < 32; kk += 8) {
            uint32_t a[2][4];
#pragma unroll
            for (int mt = 0; mt < 2; mt++) {
                int r = m0 + 16 * mt + gid;
                a[mt][0] = As[r * ASTR + kk + tig];
                a[mt][1] = As[(r + 8) * ASTR + kk + tig];
                a[mt][2] = As[r * ASTR + kk + tig + 4];
                a[mt][3] = As[(r + 8) * ASTR + kk + tig + 4];
            }
            uint32_t b[8][2];
#pragma unroll
            for (int nt = 0; nt < 8; nt++) {
                int n = 8 * nt + gid;
                b[nt][0] = Bs[n * ASTR + kk + tig];
                b[nt][1] = Bs[n * ASTR + kk + tig + 4];
            }
#pragma unroll
            for (int mt = 0; mt < 2; mt++)
#pragma unroll
                for (int nt = 0; nt < 8; nt++)
                    asm volatile(
                        "mma.sync.aligned.m16n8k8.row.col.f32.tf32.tf32.f32 "
                        "{%0,%1,%2,%3}, {%4,%5,%6,%7}, {%8,%9}, {%0,%1,%2,%3};"
                        : "+f"(acc[mt][nt][0]), "+f"(acc[mt][nt][1]),
                          "+f"(acc[mt][nt][2]), "+f"(acc[mt][nt][3])
                        : "r"(a[mt][0]), "r"(a[mt][1]), "r"(a[mt][2]), "r"(a[mt][3]),
                          "r"(b[nt][0]), "r"(b[nt][1]));
        }
        __syncthreads();         // buffer j&3 reused by load at iter j+1
    }

    // ---- scatter logits to smem transposed (stride 65), scaled ----
    float* sl = (float*)(smem + SM_L);
#pragma unroll
    for (int mt = 0; mt < 2; mt++)
#pragma unroll
        for (int nt = 0; nt < 8; nt++)
#pragma unroll
            for (int c = 0; c < 4; c++) {
                int row = m0 + 16 * mt + gid + 8 * (c >> 1);   // feature (0..127)
                int col = 8 * nt + 2 * tig + (c & 1);          // batch  (0..63)
                sl[row * 65 + col] = acc[mt][nt][c] * invn[col] * TINV;
            }
    __syncthreads();

    // ---- per-batch partials over this CTA's 128 feature rows (two halves) ----
    {
        const int m = tid & 63;
        const int h = tid >> 6;
        const int f0 = h * 64;
        float mx = -3.4e38f;
#pragma unroll 8
        for (int f = 0; f < 64; f++) mx = fmaxf(mx, sl[(f0 + f) * 65 + m]);
        float se = 0.f, W = 0.f, Zt = 0.f;
        const float* tr = targets + (size_t)m * N_ + n0 + f0;
        for (int f = 0; f < 64; f += 4) {
            float4 t4 = *(const float4*)(tr + f);
            float l0 = sl[(f0 + f + 0) * 65 + m];
            float l1 = sl[(f0 + f + 1) * 65 + m];
            float l2 = sl[(f0 + f + 2) * 65 + m];
            float l3 = sl[(f0 + f + 3) * 65 + m];
            se += __expf(l0 - mx) + __expf(l1 - mx) + __expf(l2 - mx) + __expf(l3 - mx);
            float e0 = __expf(t4.x), e1 = __expf(t4.y), e2 = __expf(t4.z), e3 = __expf(t4.w);
            W  += e0 * l0 + e1 * l1 + e2 * l2 + e3 * l3;
            Zt += e0 + e1 + e2 + e3;
        }
        float4* hp = (float4*)(smem + SM_HALF);
        if (h == 1) hp[m] = make_float4(mx, se, W, Zt);
        __syncthreads();
        if (h == 0) {
            float4 q = hp[m];
            float nm = fmaxf(mx, q.x);
            se = se * __expf(mx - nm) + q.y * __expf(q.x - nm);
            g_part[(size_t)m * NBLK_ + blockIdx.x] =
                make_float4(nm, se, W + q.z, Zt + q.w);
        }
    }
}

// ---------------------------------------------------------------------------
// Kernel 3: per-row merge of 128 block partials -> row loss = lse - W/Zt
// ---------------------------------------------------------------------------
__global__ void rowred_kernel() {
    const int m = blockIdx.x;
    const int t = threadIdx.x;   // 128 threads
    float4 p = g_part[(size_t)m * NBLK_ + t];
    float mx = p.x, se = p.y, W = p.z, Zt = p.w;
#pragma unroll
    for (int off = 16; off; off >>= 1) {
        float omx = __shfl_xor_sync(0xffffffffu, mx, off);
        float ose = __shfl_xor_sync(0xffffffffu, se, off);
        float oW  = __shfl_xor_sync(0xffffffffu, W,  off);
        float oZ  = __shfl_xor_sync(0xffffffffu, Zt, off);
        float nm = fmaxf(mx, omx);
        se = se * expf(mx - nm) + ose * expf(omx - nm);
        mx = nm; W += oW; Zt += oZ;
    }
    __shared__ float4 red[4];
    if ((t & 31) == 0) red[t >> 5] = make_float4(mx, se, W, Zt);
    __syncthreads();
    if (t == 0) {
        mx = red[0].x; se = red[0].y; W = red[0].z; Zt = red[0].w;
#pragma unroll
        for (int w = 1; w < 4; w++) {
            float4 q = red[w];
            float nm = fmaxf(mx, q.x);
            se = se * expf(mx - nm) + q.y * expf(q.x - nm);
            mx = nm; W += q.z; Zt += q.w;
        }
        g_row_loss[m] = (mx + logf(se)) - W / Zt;
    }
}

// ---------------------------------------------------------------------------
// Kernel 4: deterministic final sum / B
// ---------------------------------------------------------------------------
__global__ void final_kernel(float* out) {
    const int t = threadIdx.x;   // 64 threads
    float v = g_row_loss[t];
#pragma unroll
    for (int off = 16; off; off >>= 1) v += __shfl_xor_sync(0xffffffffu, v, off);
    __shared__ float w0;
    if (t == 0) w0 = v;
    __syncthreads();
    if (t == 32) out[0] = (v + w0) * (1.0f / B_);
}

// ---------------------------------------------------------------------------
extern "C" void kernel_launch(void* const* d_in, const int* in_sizes, int n_in,
                              void* d_out, int out_size) {
    const float* x  = nullptr;
    const float* tg = nullptr;
    const float* ft = nullptr;
    for (int i = 0; i < n_in; i++) {
        if      (in_sizes[i] == B_ * D_) x  = (const float*)d_in[i];
        else if (in_sizes[i] == B_ * N_) tg = (const float*)d_in[i];
        else if (in_sizes[i] == N_ * D_) ft = (const float*)d_in[i];
    }

    cudaFuncSetAttribute(mma_kernel, cudaFuncAttributeMaxDynamicSharedMemorySize,
                         SMEM_TOTAL);

    norm_kernel<<<B_, 256>>>(x);
    mma_kernel<<<NBLK_, 128, SMEM_TOTAL>>>(x, ft, tg);
    rowred_kernel<<<B_, 128>>>();
    final_kernel<<<1, 64>>>((float*)d_out);
}